// round 7
// baseline (speedup 1.0000x reference)
#include <cuda_runtime.h>
#include <cuda_bf16.h>
#include <math.h>
#include <stdint.h>

#define B_ROWS 16384
#define IN_DIM 768
#define ENC_DIM 500
#define ZE_NPAD 512
#define KCLS 43
#define VDIM 1024
#define CAT_RAW 1067
#define CAT_LD  1088   // multiple of 64

// ---------------- scratch (bf16 pairs stored as uint32) ----------------
__device__ uint32_t g_xh [(size_t)B_ROWS * IN_DIM / 2];
__device__ uint32_t g_xl [(size_t)B_ROWS * IN_DIM / 2];
__device__ uint32_t g_weh[(size_t)ZE_NPAD * IN_DIM / 2];
__device__ uint32_t g_wel[(size_t)ZE_NPAD * IN_DIM / 2];
__device__ uint32_t g_w1h[(size_t)VDIM * IN_DIM / 2];
__device__ uint32_t g_w1l[(size_t)VDIM * IN_DIM / 2];
__device__ uint32_t g_w2h[(size_t)2 * VDIM * VDIM / 2];   // interleaved rows
__device__ uint32_t g_w2l[(size_t)2 * VDIM * VDIM / 2];
__device__ uint32_t g_wdh[(size_t)IN_DIM * CAT_LD / 2];
__device__ uint32_t g_wdl[(size_t)IN_DIM * CAT_LD / 2];
__device__ uint32_t g_hh [(size_t)B_ROWS * VDIM / 2];
__device__ uint32_t g_hl [(size_t)B_ROWS * VDIM / 2];
__device__ uint32_t g_cath[(size_t)B_ROWS * CAT_LD / 2];
__device__ uint32_t g_catl[(size_t)B_ROWS * CAT_LD / 2];
__device__ float g_G  [(size_t)KCLS * IN_DIM];
__device__ float g_lb [KCLS];
__device__ float g_klq[2048 * 256];          // per-thread KL partials from ml epilogue
__device__ float g_ze_s[(size_t)B_ROWS * ENC_DIM];
__device__ float g_zq_s[(size_t)B_ROWS * ENC_DIM];
__device__ float g_lg_s[(size_t)B_ROWS * KCLS];
__device__ float g_kl_s[1];
__device__ int   g_mask_mode;

// ---------------- helpers ----------------
__device__ __forceinline__ uint32_t smem_to_u32(const void* p) {
    uint32_t a;
    asm("{ .reg .u64 t; cvta.to.shared.u64 t, %1; cvt.u32.u64 %0, t; }" : "=r"(a) : "l"(p));
    return a;
}
#define SWZ(b) ((b) ^ (((b) >> 3) & 0x70))
#define CP16(d, s)  asm volatile("cp.async.cg.shared.global [%0], [%1], 16;" :: "r"(d), "l"(s) : "memory")
#define CP_COMMIT() asm volatile("cp.async.commit_group;" ::: "memory")
#define CP_WAIT0()  asm volatile("cp.async.wait_group 0;" ::: "memory")
#define CP_WAIT1()  asm volatile("cp.async.wait_group 1;" ::: "memory")

__device__ __forceinline__ void ldsm_x4(uint32_t* r, uint32_t addr) {
    asm volatile("ldmatrix.sync.aligned.m8n8.x4.shared.b16 {%0,%1,%2,%3}, [%4];"
        : "=r"(r[0]), "=r"(r[1]), "=r"(r[2]), "=r"(r[3]) : "r"(addr));
}
__device__ __forceinline__ void mma16816(float* c, const uint32_t* a, const uint32_t* b) {
    asm volatile("mma.sync.aligned.m16n8k16.row.col.f32.bf16.bf16.f32 "
        "{%0,%1,%2,%3}, {%4,%5,%6,%7}, {%8,%9}, {%0,%1,%2,%3};"
        : "+f"(c[0]), "+f"(c[1]), "+f"(c[2]), "+f"(c[3])
        : "r"(a[0]), "r"(a[1]), "r"(a[2]), "r"(a[3]), "r"(b[0]), "r"(b[1]));
}
__device__ __forceinline__ void split2(float v0, float v1, uint32_t& H, uint32_t& L) {
    uint32_t u0 = __float_as_uint(v0), u1 = __float_as_uint(v1);
    H = __byte_perm(u0, u1, 0x7632);
    float l0 = v0 - __uint_as_float(u0 & 0xFFFF0000u);
    float l1 = v1 - __uint_as_float(u1 & 0xFFFF0000u);
    asm("cvt.rn.bf16x2.f32 %0, %1, %2;" : "=r"(L) : "f"(l1), "f"(l0));
}

// ---------------- 3-stage pipelined mma.sync bf16x3 GEMM ----------------
// C[M,N] = A[M,K] @ B[N,K]^T + bias. A,B pre-split bf16 hi/lo.
// CTA 128x128, 8 warps, warp tile 64x32, K chunk 64, 3-stage cp.async,
// one __syncthreads per chunk.
#define ST_BYTES 65536u
#define GEMM_DYN (3 * 65536 + 1024)

__device__ __forceinline__ void load_chunk(uint32_t base, int tid, int m0, int n0, int k0,
    const uint16_t* Ah, const uint16_t* Al, int lda,
    const uint16_t* Bh, const uint16_t* Bl, int ldb)
{
#pragma unroll
    for (int it = 0; it < 4; it++) {
        int idx = it * 256 + tid;
        int row = idx >> 3, u = idx & 7;
        uint32_t off = SWZ((uint32_t)(row * 128 + u * 16));
        size_t ao = (size_t)(m0 + row) * lda + k0 + u * 8;
        size_t bo = (size_t)(n0 + row) * ldb + k0 + u * 8;
        CP16(base + off,           Ah + ao);
        CP16(base + 16384u + off,  Al + ao);
        CP16(base + 32768u + off,  Bh + bo);
        CP16(base + 49152u + off,  Bl + bo);
    }
}

// mode: 0 = fp32 C (+bias,+relu,col-guard), 1 = split bf16 hi/lo C, 2 = fused VAE epilogue
__global__ __launch_bounds__(256, 1)
void gemm_bf3(const uint16_t* __restrict__ Ah, const uint16_t* __restrict__ Al, int lda,
              const uint16_t* __restrict__ Bh, const uint16_t* __restrict__ Bl, int ldb,
              const float* __restrict__ bias,
              float* __restrict__ Cf, uint16_t* __restrict__ Ch, uint16_t* __restrict__ Cl,
              int ldc, int nOut, int K, int relu, int mode,
              const float* __restrict__ eps, float* __restrict__ klq)
{
    extern __shared__ char smem[];
    const uint32_t tiles = (smem_to_u32(smem) + 1023) & ~1023u;
    const int tid = threadIdx.x, wid = tid >> 5, lane = tid & 31;
    const int m0 = blockIdx.y * 128, n0 = blockIdx.x * 128;
    const int wm = (wid >> 2) * 64, wn = (wid & 3) * 32;

    float acc[4][4][4];
#pragma unroll
    for (int i = 0; i < 4; i++)
#pragma unroll
        for (int j = 0; j < 4; j++)
#pragma unroll
            for (int q = 0; q < 4; q++) acc[i][j][q] = 0.f;

    const uint32_t aRowByte = (uint32_t)(wm + (lane & 15)) * 128u;
    const uint32_t aKoff    = (uint32_t)((lane >> 4) * 16);
    const uint32_t bRowByte = (uint32_t)(wn + (lane & 7) + ((lane >> 4) << 3)) * 128u;
    const uint32_t bKoff    = (uint32_t)(((lane >> 3) & 1) * 16);

    const int S = K / 64;
    load_chunk(tiles, tid, m0, n0, 0, Ah, Al, lda, Bh, Bl, ldb);
    CP_COMMIT();
    if (S > 1) {
        load_chunk(tiles + ST_BYTES, tid, m0, n0, 64, Ah, Al, lda, Bh, Bl, ldb);
        CP_COMMIT();
    }

    int stg = 0;
    for (int s = 0; s < S; s++) {
        if (s + 1 < S) CP_WAIT1(); else CP_WAIT0();
        __syncthreads();
        if (s + 2 < S) {
            int ns = stg + 2; if (ns >= 3) ns -= 3;
            load_chunk(tiles + (uint32_t)ns * ST_BYTES, tid, m0, n0, (s + 2) * 64,
                       Ah, Al, lda, Bh, Bl, ldb);
            CP_COMMIT();
        }
        const uint32_t pah = tiles + (uint32_t)stg * ST_BYTES;
        const uint32_t pal = pah + 16384u, pbh = pah + 32768u, pbl = pah + 49152u;
#pragma unroll
        for (int kk = 0; kk < 4; kk++) {
            const uint32_t kb = (uint32_t)(kk * 32);
            uint32_t ah[4][4], al[4][4], bh[2][4], bl[2][4];
#pragma unroll
            for (int mt = 0; mt < 4; mt++) {
                uint32_t ro = SWZ(aRowByte + (uint32_t)(mt * 2048) + kb + aKoff);
                ldsm_x4(ah[mt], pah + ro);
                ldsm_x4(al[mt], pal + ro);
            }
#pragma unroll
            for (int nb = 0; nb < 2; nb++) {
                uint32_t ro = SWZ(bRowByte + (uint32_t)(nb * 2048) + kb + bKoff);
                ldsm_x4(bh[nb], pbh + ro);
                ldsm_x4(bl[nb], pbl + ro);
            }
#pragma unroll
            for (int mt = 0; mt < 4; mt++)
#pragma unroll
                for (int nt = 0; nt < 4; nt++) {
                    const uint32_t* bhp = &bh[nt >> 1][(nt & 1) * 2];
                    const uint32_t* blp = &bl[nt >> 1][(nt & 1) * 2];
                    mma16816(acc[mt][nt], ah[mt], bhp);
                    mma16816(acc[mt][nt], al[mt], bhp);
                    mma16816(acc[mt][nt], ah[mt], blp);
                }
        }
        if (++stg == 3) stg = 0;
    }

    // ---- epilogue ----
    if (mode == 0) {
#pragma unroll
        for (int mt = 0; mt < 4; mt++) {
            const int r0 = m0 + wm + mt * 16 + (lane >> 2);
            float* crow0 = Cf + (size_t)r0 * ldc;
            float* crow8 = Cf + (size_t)(r0 + 8) * ldc;
#pragma unroll
            for (int nt = 0; nt < 4; nt++) {
                const int c = n0 + wn + nt * 8 + (lane & 3) * 2;
                if (c >= nOut) continue;
                float b0 = bias[c], b1 = bias[c + 1];
                float v0 = acc[mt][nt][0] + b0, v1 = acc[mt][nt][1] + b1;
                float v2 = acc[mt][nt][2] + b0, v3 = acc[mt][nt][3] + b1;
                if (relu) {
                    v0 = fmaxf(v0, 0.f); v1 = fmaxf(v1, 0.f);
                    v2 = fmaxf(v2, 0.f); v3 = fmaxf(v3, 0.f);
                }
                *reinterpret_cast<float2*>(crow0 + c) = make_float2(v0, v1);
                *reinterpret_cast<float2*>(crow8 + c) = make_float2(v2, v3);
            }
        }
    } else if (mode == 1) {
#pragma unroll
        for (int mt = 0; mt < 4; mt++) {
            const int r0 = m0 + wm + mt * 16 + (lane >> 2);
#pragma unroll
            for (int nt = 0; nt < 4; nt++) {
                const int c = n0 + wn + nt * 8 + (lane & 3) * 2;
                float b0 = bias[c], b1 = bias[c + 1];
                float v0 = acc[mt][nt][0] + b0, v1 = acc[mt][nt][1] + b1;
                float v2 = acc[mt][nt][2] + b0, v3 = acc[mt][nt][3] + b1;
                if (relu) {
                    v0 = fmaxf(v0, 0.f); v1 = fmaxf(v1, 0.f);
                    v2 = fmaxf(v2, 0.f); v3 = fmaxf(v3, 0.f);
                }
                uint32_t H, L;
                split2(v0, v1, H, L);
                *reinterpret_cast<uint32_t*>(Ch + (size_t)r0 * ldc + c) = H;
                *reinterpret_cast<uint32_t*>(Cl + (size_t)r0 * ldc + c) = L;
                split2(v2, v3, H, L);
                *reinterpret_cast<uint32_t*>(Ch + (size_t)(r0 + 8) * ldc + c) = H;
                *reinterpret_cast<uint32_t*>(Cl + (size_t)(r0 + 8) * ldc + c) = L;
            }
        }
    } else {
        // mode 2: cols are interleaved (mu_i, logvar_i) pairs; produce sampled_z
        // into cat (bf16 hi/lo scalars, element index i), accumulate KL partials.
        float klsum = 0.f;
#pragma unroll
        for (int mt = 0; mt < 4; mt++) {
            const int r0 = m0 + wm + mt * 16 + (lane >> 2);
#pragma unroll
            for (int nt = 0; nt < 4; nt++) {
                const int c = n0 + wn + nt * 8 + (lane & 3) * 2;
                const int i = c >> 1;
                float bmu = bias[i], blv = bias[VDIM + i];
#pragma unroll
                for (int h = 0; h < 2; h++) {
                    const int r = r0 + h * 8;
                    float mu = acc[mt][nt][2 * h + 0] + bmu;
                    float lv = acc[mt][nt][2 * h + 1] + blv;
                    klsum += 0.5f * (expf(lv) + mu * mu - 1.0f - lv);
                    float z = fmaf(expf(0.5f * lv), eps[(size_t)r * VDIM + i], mu);
                    uint32_t uz = __float_as_uint(z);
                    float zl = z - __uint_as_float(uz & 0xFFFF0000u);
                    Ch[(size_t)r * ldc + i] = (uint16_t)(uz >> 16);
                    Cl[(size_t)r * ldc + i] = __bfloat16_as_ushort(__float2bfloat16(zl));
                }
            }
        }
        klq[((size_t)blockIdx.y * gridDim.x + blockIdx.x) * 256 + tid] = klsum;
    }
}

// ---------------- logits SGEMM: 64x64 tile, exact fp32 ----------------
__global__ __launch_bounds__(128)
void sgemm64(const float* __restrict__ A, const float* __restrict__ G,
             const float* __restrict__ lb, float* __restrict__ C)
{
    __shared__ float As[16][64];
    __shared__ float Bs[16][64];
    const int tid = threadIdx.x;
    const int m0 = blockIdx.x * 64;
    const int tx = tid & 15, ty = tid >> 4;
    const int lrow = tid >> 1, lhalf = tid & 1;
    float acc[8][4];
#pragma unroll
    for (int i = 0; i < 8; i++)
#pragma unroll
        for (int j = 0; j < 4; j++) acc[i][j] = 0.f;

    for (int k0 = 0; k0 < IN_DIM; k0 += 16) {
#pragma unroll
        for (int h = 0; h < 2; h++) {
            int kk = lhalf * 8 + h * 4;
            float4 va = *reinterpret_cast<const float4*>(A + (size_t)(m0 + lrow) * IN_DIM + k0 + kk);
            As[kk + 0][lrow] = va.x; As[kk + 1][lrow] = va.y;
            As[kk + 2][lrow] = va.z; As[kk + 3][lrow] = va.w;
            float4 vb = make_float4(0.f, 0.f, 0.f, 0.f);
            if (lrow < KCLS)
                vb = *reinterpret_cast<const float4*>(G + (size_t)lrow * IN_DIM + k0 + kk);
            Bs[kk + 0][lrow] = vb.x; Bs[kk + 1][lrow] = vb.y;
            Bs[kk + 2][lrow] = vb.z; Bs[kk + 3][lrow] = vb.w;
        }
        __syncthreads();
#pragma unroll
        for (int k = 0; k < 16; k++) {
            float4 a0 = *reinterpret_cast<const float4*>(&As[k][ty * 4]);
            float4 a1 = *reinterpret_cast<const float4*>(&As[k][32 + ty * 4]);
            float4 b  = *reinterpret_cast<const float4*>(&Bs[k][tx * 4]);
            float a[8] = {a0.x, a0.y, a0.z, a0.w, a1.x, a1.y, a1.z, a1.w};
            float bb[4] = {b.x, b.y, b.z, b.w};
#pragma unroll
            for (int i = 0; i < 8; i++)
#pragma unroll
                for (int j = 0; j < 4; j++)
                    acc[i][j] = fmaf(a[i], bb[j], acc[i][j]);
        }
        __syncthreads();
    }
#pragma unroll
    for (int i = 0; i < 8; i++) {
        int row = m0 + ((i < 4) ? (ty * 4 + i) : (32 + ty * 4 + i - 4));
#pragma unroll
        for (int j = 0; j < 4; j++) {
            int col = tx * 4 + j;
            if (col < KCLS) C[(size_t)row * KCLS + col] = acc[i][j] + lb[col];
        }
    }
}

// ---------------- prep kernels ----------------
__global__ void split_mat(const float* __restrict__ src, uint32_t* __restrict__ dh,
                          uint32_t* __restrict__ dl, long nPairs, long srcPairs)
{
    long i = (long)blockIdx.x * blockDim.x + threadIdx.x;
    if (i >= nPairs) return;
    float v0 = 0.f, v1 = 0.f;
    if (i < srcPairs) {
        float2 v = reinterpret_cast<const float2*>(src)[i];
        v0 = v.x; v1 = v.y;
    }
    uint32_t H, L;
    split2(v0, v1, H, L);
    dh[i] = H; dl[i] = L;
}

// interleave W2 rows (out row 2i = mu row i, 2i+1 = logvar row 1024+i) + split
__global__ void split_w2(const float* __restrict__ W2)
{
    int i = blockIdx.x * blockDim.x + threadIdx.x;
    const int ppr = VDIM / 2;
    if (i >= 2 * VDIM * ppr) return;
    int rr = i / ppr, p = i - rr * ppr;
    int orig = (rr & 1) ? (VDIM + (rr >> 1)) : (rr >> 1);
    float2 v = *reinterpret_cast<const float2*>(W2 + (size_t)orig * VDIM + 2 * p);
    uint32_t H, L;
    split2(v.x, v.y, H, L);
    g_w2h[i] = H; g_w2l[i] = L;
}

__global__ void split_wd(const float* __restrict__ Wd)
{
    int i = blockIdx.x * blockDim.x + threadIdx.x;
    const int ppr = CAT_LD / 2;
    if (i >= IN_DIM * ppr) return;
    int r = i / ppr, p = i - r * ppr;
    int c0 = 2 * p;
    float v0 = (c0 < CAT_RAW) ? Wd[(size_t)r * CAT_RAW + c0] : 0.f;
    float v1 = (c0 + 1 < CAT_RAW) ? Wd[(size_t)r * CAT_RAW + c0 + 1] : 0.f;
    uint32_t H, L;
    split2(v0, v1, H, L);
    g_wdh[i] = H; g_wdl[i] = L;
}

__global__ void build_G(const float* __restrict__ W_enc, const float* __restrict__ cb)
{
    int c = blockIdx.x;
    int i = blockIdx.y * 128 + threadIdx.x;
    float s = 0.f;
#pragma unroll 4
    for (int d = 0; d < ENC_DIM; d++)
        s = fmaf(cb[c * ENC_DIM + d], W_enc[(size_t)d * IN_DIM + i], s);
    g_G[(size_t)c * IN_DIM + i] = s;
}
__global__ void build_lb(const float* __restrict__ b_enc, const float* __restrict__ cb)
{
    int c = blockIdx.x;
    int t = threadIdx.x;
    float s = 0.f;
    for (int d = t; d < ENC_DIM; d += 128) s = fmaf(b_enc[d], cb[c * ENC_DIM + d], s);
    __shared__ float sm[128];
    sm[t] = s;
    __syncthreads();
    for (int st = 64; st > 0; st >>= 1) { if (t < st) sm[t] += sm[t + st]; __syncthreads(); }
    if (t == 0) g_lb[c] = sm[0];
}

__global__ void detect_mask_kernel(const unsigned int* __restrict__ w)
{
    __shared__ int s_int, s_flt;
    if (threadIdx.x == 0) { s_int = 1; s_flt = 1; }
    __syncthreads();
    int li = 1, lf = 1;
    for (int i = threadIdx.x; i < 4096; i += blockDim.x) {
        unsigned v = w[i];
        if (v > 1u) li = 0;
        if (v != 0u && v != 0x3F800000u) lf = 0;
    }
    if (!li) atomicAnd(&s_int, 0);
    if (!lf) atomicAnd(&s_flt, 0);
    __syncthreads();
    if (threadIdx.x == 0) g_mask_mode = s_int ? 1 : (s_flt ? 2 : 0);
}

__global__ void argmax_y_kernel(const float* __restrict__ logits,
                                const void* __restrict__ mask,
                                const int* __restrict__ labels,
                                const float* __restrict__ codebook,
                                float* __restrict__ zq)
{
    const int b = blockIdx.x;
    const int lane = threadIdx.x;
    const float NEG = __int_as_float(0xff800000u);
    const float* lr = logits + (size_t)b * KCLS;
    const int k0 = 2 * lane, k1 = 2 * lane + 1;
    float va = (k0 < KCLS) ? lr[k0] : NEG;
    float vb = (k1 < KCLS) ? lr[k1] : NEG;
    float m; int mi;
    if (va >= vb) { m = va; mi = k0; } else { m = vb; mi = k1; }
#pragma unroll
    for (int off = 16; off > 0; off >>= 1) {
        float om = __shfl_xor_sync(0xffffffffu, m, off);
        int oi = __shfl_xor_sync(0xffffffffu, mi, off);
        if (om > m || (om == m && oi < mi)) { m = om; mi = oi; }
    }
    float ea = (k0 < KCLS) ? expf(va - m) : 0.f;
    float eb = (k1 < KCLS) ? expf(vb - m) : 0.f;
    float s = ea + eb;
#pragma unroll
    for (int off = 16; off > 0; off >>= 1) s += __shfl_xor_sync(0xffffffffu, s, off);
    float inv = 1.0f / s;

    int mode = g_mask_mode;
    bool known;
    if (mode == 1)      known = ((const int*)mask)[b] != 0;
    else if (mode == 2) known = ((const float*)mask)[b] != 0.f;
    else                known = ((const unsigned char*)mask)[b] != 0;
    int lab = labels[b];

    float y0 = (k0 < KCLS) ? (known ? (k0 == lab ? 1.f : 0.f) : ea * inv) : 0.f;
    float y1 = (k1 < KCLS) ? (known ? (k1 == lab ? 1.f : 0.f) : eb * inv) : 0.f;
    uint32_t H, L;
    split2(y0, y1, H, L);
    const size_t pi = (size_t)b * (CAT_LD / 2) + (VDIM / 2) + lane;
    g_cath[pi] = H; g_catl[pi] = L;

    const float* cr = codebook + (size_t)mi * ENC_DIM;
    float* zr = zq + (size_t)b * ENC_DIM;
    for (int i = lane; i < ENC_DIM; i += 32) zr[i] = cr[i];
}

__global__ void kl_reduce_kernel(float* __restrict__ out)
{
    const int t = threadIdx.x;
    const int N = 2048 * 256;
    float s = 0.f;
    for (int i = t; i < N; i += 256) s += g_klq[i];
    __shared__ float sm[256];
    sm[t] = s;
    __syncthreads();
    for (int st = 128; st > 0; st >>= 1) { if (t < st) sm[t] += sm[t + st]; __syncthreads(); }
    if (t == 0) *out = sm[0] / (float)B_ROWS;
}

// ---------------- host ----------------
static void launch_gemm(const void* Ah, const void* Al, int lda,
                        const void* Bh, const void* Bl, int ldb,
                        const float* bias, float* Cf, void* Ch, void* Cl,
                        int ldc, int nPad, int nOut, int K, int relu, int mode,
                        const float* eps, float* klq)
{
    cudaFuncSetAttribute(gemm_bf3, cudaFuncAttributeMaxDynamicSharedMemorySize, GEMM_DYN);
    dim3 grid(nPad / 128, B_ROWS / 128);
    gemm_bf3<<<grid, 256, GEMM_DYN>>>(
        (const uint16_t*)Ah, (const uint16_t*)Al, lda,
        (const uint16_t*)Bh, (const uint16_t*)Bl, ldb,
        bias, Cf, (uint16_t*)Ch, (uint16_t*)Cl, ldc, nOut, K, relu, mode, eps, klq);
}

extern "C" void kernel_launch(void* const* d_in, const int* in_sizes, int n_in,
                              void* d_out, int out_size)
{
    const float* x        = (const float*)d_in[0];
    const void*  mask     = d_in[1];
    const int*   labels   = (const int*)d_in[2];
    const float* eps      = (const float*)d_in[3];
    const float* W_enc    = (const float*)d_in[4];
    const float* b_enc    = (const float*)d_in[5];
    const float* codebook = (const float*)d_in[6];
    const float* W1       = (const float*)d_in[7];
    const float* b1       = (const float*)d_in[8];
    const float* W2       = (const float*)d_in[9];
    const float* b2       = (const float*)d_in[10];
    const float* Wd       = (const float*)d_in[11];
    const float* bd       = (const float*)d_in[12];
    float* out = (float*)d_out;

    void *p_xh, *p_xl, *p_weh, *p_wel, *p_w1h, *p_w1l, *p_wdh, *p_wdl;
    void *p_w2h, *p_w2l, *p_hh, *p_hl, *p_cath, *p_catl;
    float *p_G, *p_lb, *p_klq, *p_ze, *p_zq, *p_lg, *p_kl;
    cudaGetSymbolAddress(&p_xh, g_xh);   cudaGetSymbolAddress(&p_xl, g_xl);
    cudaGetSymbolAddress(&p_weh, g_weh); cudaGetSymbolAddress(&p_wel, g_wel);
    cudaGetSymbolAddress(&p_w1h, g_w1h); cudaGetSymbolAddress(&p_w1l, g_w1l);
    cudaGetSymbolAddress(&p_w2h, g_w2h); cudaGetSymbolAddress(&p_w2l, g_w2l);
    cudaGetSymbolAddress(&p_wdh, g_wdh); cudaGetSymbolAddress(&p_wdl, g_wdl);
    cudaGetSymbolAddress(&p_hh, g_hh);   cudaGetSymbolAddress(&p_hl, g_hl);
    cudaGetSymbolAddress(&p_cath, g_cath); cudaGetSymbolAddress(&p_catl, g_catl);
    cudaGetSymbolAddress((void**)&p_G,  g_G);
    cudaGetSymbolAddress((void**)&p_lb, g_lb);
    cudaGetSymbolAddress((void**)&p_klq, g_klq);
    cudaGetSymbolAddress((void**)&p_ze, g_ze_s);
    cudaGetSymbolAddress((void**)&p_zq, g_zq_s);
    cudaGetSymbolAddress((void**)&p_lg, g_lg_s);
    cudaGetSymbolAddress((void**)&p_kl, g_kl_s);

    const size_t full_elems = (size_t)B_ROWS * (IN_DIM + ENC_DIM + ENC_DIM + KCLS) + 1;
    const bool full = ((size_t)out_size >= full_elems);
    float* xt = out;
    float* ze = full ? out + (size_t)B_ROWS * IN_DIM : p_ze;
    float* zq = full ? ze + (size_t)B_ROWS * ENC_DIM : p_zq;
    float* lg = full ? zq + (size_t)B_ROWS * ENC_DIM : p_lg;
    float* kl = full ? lg + (size_t)B_ROWS * KCLS    : p_kl;

    // ---- prep ----
    {
        long np = (long)B_ROWS * IN_DIM / 2;
        split_mat<<<(unsigned)((np + 255) / 256), 256>>>(x, (uint32_t*)p_xh, (uint32_t*)p_xl, np, np);
        long sp = (long)ENC_DIM * IN_DIM / 2, tp = (long)ZE_NPAD * IN_DIM / 2;
        split_mat<<<(unsigned)((tp + 255) / 256), 256>>>(W_enc, (uint32_t*)p_weh, (uint32_t*)p_wel, tp, sp);
        long w1p = (long)VDIM * IN_DIM / 2;
        split_mat<<<(unsigned)((w1p + 255) / 256), 256>>>(W1, (uint32_t*)p_w1h, (uint32_t*)p_w1l, w1p, w1p);
        split_w2<<<(2 * VDIM * (VDIM / 2) + 255) / 256, 256>>>(W2);
        split_wd<<<(IN_DIM * (CAT_LD / 2) + 255) / 256, 256>>>(Wd);
    }
    detect_mask_kernel<<<1, 256>>>((const unsigned int*)mask);
    build_G<<<dim3(KCLS, IN_DIM / 128), 128>>>(W_enc, codebook);
    build_lb<<<KCLS, 128>>>(b_enc, codebook);

    // logits (exact fp32 via G = codebook @ W_enc)
    sgemm64<<<B_ROWS / 64, 128>>>(x, p_G, p_lb, lg);

    // z_e_x
    launch_gemm(p_xh, p_xl, IN_DIM, p_weh, p_wel, IN_DIM, b_enc,
                ze, nullptr, nullptr, ENC_DIM, ZE_NPAD, ENC_DIM, IN_DIM, 0, 0, nullptr, nullptr);
    // h = relu(x@W1^T + b1) -> bf16 hi/lo
    launch_gemm(p_xh, p_xl, IN_DIM, p_w1h, p_w1l, IN_DIM, b1,
                nullptr, p_hh, p_hl, VDIM, VDIM, VDIM, IN_DIM, 1, 1, nullptr, nullptr);
    // mu||logvar interleaved -> fused reparam + KL into cat
    launch_gemm(p_hh, p_hl, VDIM, p_w2h, p_w2l, VDIM, b2,
                nullptr, p_cath, p_catl, CAT_LD, 2 * VDIM, 2 * VDIM, VDIM, 0, 2, eps, p_klq);

    // argmax / y / z_q (fills cat y region)
    argmax_y_kernel<<<B_ROWS, 32>>>(lg, mask, labels, codebook, zq);
    kl_reduce_kernel<<<1, 256>>>(kl);

    // decoder
    launch_gemm(p_cath, p_catl, CAT_LD, p_wdh, p_wdl, CAT_LD, bd,
                xt, nullptr, nullptr, IN_DIM, IN_DIM, IN_DIM, CAT_LD, 0, 0, nullptr, nullptr);
}

// round 8
// speedup vs baseline: 1.1178x; 1.1178x over previous
#include <cuda_runtime.h>
#include <cuda_bf16.h>
#include <math.h>
#include <stdint.h>

#define B_ROWS 16384
#define IN_DIM 768
#define ENC_DIM 500
#define ZE_NPAD 512
#define KCLS 43
#define VDIM 1024
#define CAT_RAW 1067
#define CAT_LD  1088   // multiple of 64

// ---------------- scratch (bf16 pairs stored as uint32) ----------------
__device__ uint32_t g_xh [(size_t)B_ROWS * IN_DIM / 2];
__device__ uint32_t g_xl [(size_t)B_ROWS * IN_DIM / 2];
__device__ uint32_t g_weh[(size_t)ZE_NPAD * IN_DIM / 2];
__device__ uint32_t g_wel[(size_t)ZE_NPAD * IN_DIM / 2];
__device__ uint32_t g_w1h[(size_t)VDIM * IN_DIM / 2];
__device__ uint32_t g_w1l[(size_t)VDIM * IN_DIM / 2];
__device__ uint32_t g_w2h[(size_t)2 * VDIM * VDIM / 2];
__device__ uint32_t g_w2l[(size_t)2 * VDIM * VDIM / 2];
__device__ uint32_t g_wdh[(size_t)IN_DIM * CAT_LD / 2];
__device__ uint32_t g_wdl[(size_t)IN_DIM * CAT_LD / 2];
__device__ uint32_t g_hh [(size_t)B_ROWS * VDIM / 2];
__device__ uint32_t g_hl [(size_t)B_ROWS * VDIM / 2];
__device__ uint32_t g_cath[(size_t)B_ROWS * CAT_LD / 2];
__device__ uint32_t g_catl[(size_t)B_ROWS * CAT_LD / 2];
__device__ float g_ml [(size_t)B_ROWS * 2 * VDIM];
__device__ float g_G  [(size_t)KCLS * IN_DIM];
__device__ float g_lb [KCLS];
__device__ float g_klp[B_ROWS];
__device__ float g_ze_s[(size_t)B_ROWS * ENC_DIM];
__device__ float g_zq_s[(size_t)B_ROWS * ENC_DIM];
__device__ float g_lg_s[(size_t)B_ROWS * KCLS];
__device__ float g_kl_s[1];
__device__ int   g_mask_mode;

// ---------------- helpers ----------------
__device__ __forceinline__ uint32_t smem_to_u32(const void* p) {
    uint32_t a;
    asm("{ .reg .u64 t; cvta.to.shared.u64 t, %1; cvt.u32.u64 %0, t; }" : "=r"(a) : "l"(p));
    return a;
}
#define SWZ(b) ((b) ^ (((b) >> 3) & 0x70))
#define CP16(d, s)  asm volatile("cp.async.cg.shared.global [%0], [%1], 16;" :: "r"(d), "l"(s) : "memory")
#define CP_COMMIT() asm volatile("cp.async.commit_group;" ::: "memory")
#define CP_WAIT0()  asm volatile("cp.async.wait_group 0;" ::: "memory")
#define CP_WAIT1()  asm volatile("cp.async.wait_group 1;" ::: "memory")

__device__ __forceinline__ void ldsm_x4(uint32_t* r, uint32_t addr) {
    asm volatile("ldmatrix.sync.aligned.m8n8.x4.shared.b16 {%0,%1,%2,%3}, [%4];"
        : "=r"(r[0]), "=r"(r[1]), "=r"(r[2]), "=r"(r[3]) : "r"(addr));
}
__device__ __forceinline__ void mma16816(float* c, const uint32_t* a, const uint32_t* b) {
    asm volatile("mma.sync.aligned.m16n8k16.row.col.f32.bf16.bf16.f32 "
        "{%0,%1,%2,%3}, {%4,%5,%6,%7}, {%8,%9}, {%0,%1,%2,%3};"
        : "+f"(c[0]), "+f"(c[1]), "+f"(c[2]), "+f"(c[3])
        : "r"(a[0]), "r"(a[1]), "r"(a[2]), "r"(a[3]), "r"(b[0]), "r"(b[1]));
}
__device__ __forceinline__ void split2(float v0, float v1, uint32_t& H, uint32_t& L) {
    uint32_t u0 = __float_as_uint(v0), u1 = __float_as_uint(v1);
    H = __byte_perm(u0, u1, 0x7632);
    float l0 = v0 - __uint_as_float(u0 & 0xFFFF0000u);
    float l1 = v1 - __uint_as_float(u1 & 0xFFFF0000u);
    asm("cvt.rn.bf16x2.f32 %0, %1, %2;" : "=r"(L) : "f"(l1), "f"(l0));
}
// fast exp via EX2 (rel err ~2^-22, fine under 1e-3 budget)
__device__ __forceinline__ float fast_exp(float x) {
    float r;
    asm("ex2.approx.ftz.f32 %0, %1;" : "=f"(r) : "f"(x * 1.4426950408889634f));
    return r;
}

// ---------------- 2-stage pipelined mma.sync bf16x3 GEMM (R5-proven) ----------------
#define ST_BYTES 65536u
#define GEMM_DYN (2 * 65536 + 1024)

__device__ __forceinline__ void load_chunk(uint32_t base, int tid, int m0, int n0, int k0,
    const uint16_t* Ah, const uint16_t* Al, int lda,
    const uint16_t* Bh, const uint16_t* Bl, int ldb)
{
#pragma unroll
    for (int it = 0; it < 4; it++) {
        int idx = it * 256 + tid;
        int row = idx >> 3, u = idx & 7;
        uint32_t off = SWZ((uint32_t)(row * 128 + u * 16));
        size_t ao = (size_t)(m0 + row) * lda + k0 + u * 8;
        size_t bo = (size_t)(n0 + row) * ldb + k0 + u * 8;
        CP16(base + off,           Ah + ao);
        CP16(base + 16384u + off,  Al + ao);
        CP16(base + 32768u + off,  Bh + bo);
        CP16(base + 49152u + off,  Bl + bo);
    }
}

// mode: 0 = fp32 C (+bias,+relu,col-guard), 1 = split bf16 hi/lo C
__global__ __launch_bounds__(256, 1)
void gemm_bf3(const uint16_t* __restrict__ Ah, const uint16_t* __restrict__ Al, int lda,
              const uint16_t* __restrict__ Bh, const uint16_t* __restrict__ Bl, int ldb,
              const float* __restrict__ bias,
              float* __restrict__ Cf, uint16_t* __restrict__ Ch, uint16_t* __restrict__ Cl,
              int ldc, int nOut, int K, int relu, int mode)
{
    extern __shared__ char smem[];
    const uint32_t tiles = (smem_to_u32(smem) + 1023) & ~1023u;
    const int tid = threadIdx.x, wid = tid >> 5, lane = tid & 31;
    const int m0 = blockIdx.y * 128, n0 = blockIdx.x * 128;
    const int wm = (wid >> 2) * 64, wn = (wid & 3) * 32;

    float acc[4][4][4];
#pragma unroll
    for (int i = 0; i < 4; i++)
#pragma unroll
        for (int j = 0; j < 4; j++)
#pragma unroll
            for (int q = 0; q < 4; q++) acc[i][j][q] = 0.f;

    const uint32_t aRowByte = (uint32_t)(wm + (lane & 15)) * 128u;
    const uint32_t aKoff    = (uint32_t)((lane >> 4) * 16);
    const uint32_t bRowByte = (uint32_t)(wn + (lane & 7) + ((lane >> 4) << 3)) * 128u;
    const uint32_t bKoff    = (uint32_t)(((lane >> 3) & 1) * 16);

    const int S = K / 64;
    load_chunk(tiles, tid, m0, n0, 0, Ah, Al, lda, Bh, Bl, ldb);
    CP_COMMIT();

    for (int s = 0; s < S; s++) {
        if (s + 1 < S) {
            load_chunk(tiles + ((s + 1) & 1) * ST_BYTES, tid, m0, n0, (s + 1) * 64,
                       Ah, Al, lda, Bh, Bl, ldb);
            CP_COMMIT();
            CP_WAIT1();
        } else {
            CP_WAIT0();
        }
        __syncthreads();

        const uint32_t pah = tiles + (s & 1) * ST_BYTES;
        const uint32_t pal = pah + 16384u, pbh = pah + 32768u, pbl = pah + 49152u;
#pragma unroll
        for (int kk = 0; kk < 4; kk++) {
            const uint32_t kb = (uint32_t)(kk * 32);
            uint32_t ah[4][4], al[4][4], bh[2][4], bl[2][4];
#pragma unroll
            for (int mt = 0; mt < 4; mt++) {
                uint32_t ro = SWZ(aRowByte + (uint32_t)(mt * 2048) + kb + aKoff);
                ldsm_x4(ah[mt], pah + ro);
                ldsm_x4(al[mt], pal + ro);
            }
#pragma unroll
            for (int nb = 0; nb < 2; nb++) {
                uint32_t ro = SWZ(bRowByte + (uint32_t)(nb * 2048) + kb + bKoff);
                ldsm_x4(bh[nb], pbh + ro);
                ldsm_x4(bl[nb], pbl + ro);
            }
#pragma unroll
            for (int mt = 0; mt < 4; mt++)
#pragma unroll
                for (int nt = 0; nt < 4; nt++) {
                    const uint32_t* bhp = &bh[nt >> 1][(nt & 1) * 2];
                    const uint32_t* blp = &bl[nt >> 1][(nt & 1) * 2];
                    mma16816(acc[mt][nt], ah[mt], bhp);
                    mma16816(acc[mt][nt], al[mt], bhp);
                    mma16816(acc[mt][nt], ah[mt], blp);
                }
        }
        __syncthreads();
    }

    // ---- epilogue ----
    if (mode == 0) {
#pragma unroll
        for (int mt = 0; mt < 4; mt++) {
            const int r0 = m0 + wm + mt * 16 + (lane >> 2);
            float* crow0 = Cf + (size_t)r0 * ldc;
            float* crow8 = Cf + (size_t)(r0 + 8) * ldc;
#pragma unroll
            for (int nt = 0; nt < 4; nt++) {
                const int c = n0 + wn + nt * 8 + (lane & 3) * 2;
                if (c >= nOut) continue;
                float b0 = bias[c], b1 = bias[c + 1];
                float v0 = acc[mt][nt][0] + b0, v1 = acc[mt][nt][1] + b1;
                float v2 = acc[mt][nt][2] + b0, v3 = acc[mt][nt][3] + b1;
                if (relu) {
                    v0 = fmaxf(v0, 0.f); v1 = fmaxf(v1, 0.f);
                    v2 = fmaxf(v2, 0.f); v3 = fmaxf(v3, 0.f);
                }
                *reinterpret_cast<float2*>(crow0 + c) = make_float2(v0, v1);
                *reinterpret_cast<float2*>(crow8 + c) = make_float2(v2, v3);
            }
        }
    } else {
#pragma unroll
        for (int mt = 0; mt < 4; mt++) {
            const int r0 = m0 + wm + mt * 16 + (lane >> 2);
#pragma unroll
            for (int nt = 0; nt < 4; nt++) {
                const int c = n0 + wn + nt * 8 + (lane & 3) * 2;
                float b0 = bias[c], b1 = bias[c + 1];
                float v0 = acc[mt][nt][0] + b0, v1 = acc[mt][nt][1] + b1;
                float v2 = acc[mt][nt][2] + b0, v3 = acc[mt][nt][3] + b1;
                if (relu) {
                    v0 = fmaxf(v0, 0.f); v1 = fmaxf(v1, 0.f);
                    v2 = fmaxf(v2, 0.f); v3 = fmaxf(v3, 0.f);
                }
                uint32_t H, L;
                split2(v0, v1, H, L);
                *reinterpret_cast<uint32_t*>(Ch + (size_t)r0 * ldc + c) = H;
                *reinterpret_cast<uint32_t*>(Cl + (size_t)r0 * ldc + c) = L;
                split2(v2, v3, H, L);
                *reinterpret_cast<uint32_t*>(Ch + (size_t)(r0 + 8) * ldc + c) = H;
                *reinterpret_cast<uint32_t*>(Cl + (size_t)(r0 + 8) * ldc + c) = L;
            }
        }
    }
}

// ---------------- logits SGEMM: 64x64 tile, exact fp32 ----------------
__global__ __launch_bounds__(128)
void sgemm64(const float* __restrict__ A, const float* __restrict__ G,
             const float* __restrict__ lb, float* __restrict__ C)
{
    __shared__ float As[16][64];
    __shared__ float Bs[16][64];
    const int tid = threadIdx.x;
    const int m0 = blockIdx.x * 64;
    const int tx = tid & 15, ty = tid >> 4;
    const int lrow = tid >> 1, lhalf = tid & 1;
    float acc[8][4];
#pragma unroll
    for (int i = 0; i < 8; i++)
#pragma unroll
        for (int j = 0; j < 4; j++) acc[i][j] = 0.f;

    for (int k0 = 0; k0 < IN_DIM; k0 += 16) {
#pragma unroll
        for (int h = 0; h < 2; h++) {
            int kk = lhalf * 8 + h * 4;
            float4 va = *reinterpret_cast<const float4*>(A + (size_t)(m0 + lrow) * IN_DIM + k0 + kk);
            As[kk + 0][lrow] = va.x; As[kk + 1][lrow] = va.y;
            As[kk + 2][lrow] = va.z; As[kk + 3][lrow] = va.w;
            float4 vb = make_float4(0.f, 0.f, 0.f, 0.f);
            if (lrow < KCLS)
                vb = *reinterpret_cast<const float4*>(G + (size_t)lrow * IN_DIM + k0 + kk);
            Bs[kk + 0][lrow] = vb.x; Bs[kk + 1][lrow] = vb.y;
            Bs[kk + 2][lrow] = vb.z; Bs[kk + 3][lrow] = vb.w;
        }
        __syncthreads();
#pragma unroll
        for (int k = 0; k < 16; k++) {
            float4 a0 = *reinterpret_cast<const float4*>(&As[k][ty * 4]);
            float4 a1 = *reinterpret_cast<const float4*>(&As[k][32 + ty * 4]);
            float4 b  = *reinterpret_cast<const float4*>(&Bs[k][tx * 4]);
            float a[8] = {a0.x, a0.y, a0.z, a0.w, a1.x, a1.y, a1.z, a1.w};
            float bb[4] = {b.x, b.y, b.z, b.w};
#pragma unroll
            for (int i = 0; i < 8; i++)
#pragma unroll
                for (int j = 0; j < 4; j++)
                    acc[i][j] = fmaf(a[i], bb[j], acc[i][j]);
        }
        __syncthreads();
    }
#pragma unroll
    for (int i = 0; i < 8; i++) {
        int row = m0 + ((i < 4) ? (ty * 4 + i) : (32 + ty * 4 + i - 4));
#pragma unroll
        for (int j = 0; j < 4; j++) {
            int col = tx * 4 + j;
            if (col < KCLS) C[(size_t)row * KCLS + col] = acc[i][j] + lb[col];
        }
    }
}

// ---------------- prep kernels ----------------
__global__ void split_mat(const float* __restrict__ src, uint32_t* __restrict__ dh,
                          uint32_t* __restrict__ dl, long nPairs, long srcPairs)
{
    long i = (long)blockIdx.x * blockDim.x + threadIdx.x;
    if (i >= nPairs) return;
    float v0 = 0.f, v1 = 0.f;
    if (i < srcPairs) {
        float2 v = reinterpret_cast<const float2*>(src)[i];
        v0 = v.x; v1 = v.y;
    }
    uint32_t H, L;
    split2(v0, v1, H, L);
    dh[i] = H; dl[i] = L;
}

__global__ void split_wd(const float* __restrict__ Wd)
{
    int i = blockIdx.x * blockDim.x + threadIdx.x;
    const int ppr = CAT_LD / 2;
    if (i >= IN_DIM * ppr) return;
    int r = i / ppr, p = i - r * ppr;
    int c0 = 2 * p;
    float v0 = (c0 < CAT_RAW) ? Wd[(size_t)r * CAT_RAW + c0] : 0.f;
    float v1 = (c0 + 1 < CAT_RAW) ? Wd[(size_t)r * CAT_RAW + c0 + 1] : 0.f;
    uint32_t H, L;
    split2(v0, v1, H, L);
    g_wdh[i] = H; g_wdl[i] = L;
}

__global__ void build_G(const float* __restrict__ W_enc, const float* __restrict__ cb)
{
    int c = blockIdx.x;
    int i = blockIdx.y * 128 + threadIdx.x;
    float s = 0.f;
#pragma unroll 4
    for (int d = 0; d < ENC_DIM; d++)
        s = fmaf(cb[c * ENC_DIM + d], W_enc[(size_t)d * IN_DIM + i], s);
    g_G[(size_t)c * IN_DIM + i] = s;
}
__global__ void build_lb(const float* __restrict__ b_enc, const float* __restrict__ cb)
{
    int c = blockIdx.x;
    int t = threadIdx.x;
    float s = 0.f;
    for (int d = t; d < ENC_DIM; d += 128) s = fmaf(b_enc[d], cb[c * ENC_DIM + d], s);
    __shared__ float sm[128];
    sm[t] = s;
    __syncthreads();
    for (int st = 64; st > 0; st >>= 1) { if (t < st) sm[t] += sm[t + st]; __syncthreads(); }
    if (t == 0) g_lb[c] = sm[0];
}

__global__ void detect_mask_kernel(const unsigned int* __restrict__ w)
{
    __shared__ int s_int, s_flt;
    if (threadIdx.x == 0) { s_int = 1; s_flt = 1; }
    __syncthreads();
    int li = 1, lf = 1;
    for (int i = threadIdx.x; i < 4096; i += blockDim.x) {
        unsigned v = w[i];
        if (v > 1u) li = 0;
        if (v != 0u && v != 0x3F800000u) lf = 0;
    }
    if (!li) atomicAnd(&s_int, 0);
    if (!lf) atomicAnd(&s_flt, 0);
    __syncthreads();
    if (threadIdx.x == 0) g_mask_mode = s_int ? 1 : (s_flt ? 2 : 0);
}

__global__ void argmax_y_kernel(const float* __restrict__ logits,
                                const void* __restrict__ mask,
                                const int* __restrict__ labels,
                                const float* __restrict__ codebook,
                                float* __restrict__ zq)
{
    const int b = blockIdx.x;
    const int lane = threadIdx.x;
    const float NEG = __int_as_float(0xff800000u);
    const float* lr = logits + (size_t)b * KCLS;
    const int k0 = 2 * lane, k1 = 2 * lane + 1;
    float va = (k0 < KCLS) ? lr[k0] : NEG;
    float vb = (k1 < KCLS) ? lr[k1] : NEG;
    float m; int mi;
    if (va >= vb) { m = va; mi = k0; } else { m = vb; mi = k1; }
#pragma unroll
    for (int off = 16; off > 0; off >>= 1) {
        float om = __shfl_xor_sync(0xffffffffu, m, off);
        int oi = __shfl_xor_sync(0xffffffffu, mi, off);
        if (om > m || (om == m && oi < mi)) { m = om; mi = oi; }
    }
    float ea = (k0 < KCLS) ? expf(va - m) : 0.f;
    float eb = (k1 < KCLS) ? expf(vb - m) : 0.f;
    float s = ea + eb;
#pragma unroll
    for (int off = 16; off > 0; off >>= 1) s += __shfl_xor_sync(0xffffffffu, s, off);
    float inv = 1.0f / s;

    int mode = g_mask_mode;
    bool known;
    if (mode == 1)      known = ((const int*)mask)[b] != 0;
    else if (mode == 2) known = ((const float*)mask)[b] != 0.f;
    else                known = ((const unsigned char*)mask)[b] != 0;
    int lab = labels[b];

    float y0 = (k0 < KCLS) ? (known ? (k0 == lab ? 1.f : 0.f) : ea * inv) : 0.f;
    float y1 = (k1 < KCLS) ? (known ? (k1 == lab ? 1.f : 0.f) : eb * inv) : 0.f;
    uint32_t H, L;
    split2(y0, y1, H, L);
    const size_t pi = (size_t)b * (CAT_LD / 2) + (VDIM / 2) + lane;
    g_cath[pi] = H; g_catl[pi] = L;

    const float* cr = codebook + (size_t)mi * ENC_DIM;
    float* zr = zq + (size_t)b * ENC_DIM;
    for (int i = lane; i < ENC_DIM; i += 32) zr[i] = cr[i];
}

// reparam sample (into cat hi/lo) + KL partial — high occupancy, fast exp
__global__ void vae_post_kernel(const float* __restrict__ eps)
{
    const int b = blockIdx.x;
    const int t = threadIdx.x;
    const float* mlr = g_ml + (size_t)b * (2 * VDIM);
    const float* er = eps + (size_t)b * VDIM;
    float kl = 0.f;
#pragma unroll
    for (int p = t; p < VDIM / 2; p += 256) {
        int i0 = 2 * p;
        float2 mu = *reinterpret_cast<const float2*>(mlr + i0);
        float2 lv = *reinterpret_cast<const float2*>(mlr + VDIM + i0);
        float2 ep = *reinterpret_cast<const float2*>(er + i0);
        kl += 0.5f * (fast_exp(lv.x) + mu.x * mu.x - 1.0f - lv.x);
        kl += 0.5f * (fast_exp(lv.y) + mu.y * mu.y - 1.0f - lv.y);
        float v0 = fmaf(fast_exp(0.5f * lv.x), ep.x, mu.x);
        float v1 = fmaf(fast_exp(0.5f * lv.y), ep.y, mu.y);
        uint32_t H, L;
        split2(v0, v1, H, L);
        const size_t pi = (size_t)b * (CAT_LD / 2) + p;
        g_cath[pi] = H; g_catl[pi] = L;
    }
    __shared__ float sm[256];
    sm[t] = kl;
    __syncthreads();
    for (int st = 128; st > 0; st >>= 1) { if (t < st) sm[t] += sm[t + st]; __syncthreads(); }
    if (t == 0) g_klp[b] = sm[0];
}

__global__ void kl_reduce_kernel(float* __restrict__ out)
{
    const int t = threadIdx.x;
    float s = 0.f;
    for (int i = t; i < B_ROWS; i += 256) s += g_klp[i];
    __shared__ float sm[256];
    sm[t] = s;
    __syncthreads();
    for (int st = 128; st > 0; st >>= 1) { if (t < st) sm[t] += sm[t + st]; __syncthreads(); }
    if (t == 0) *out = sm[0] / (float)B_ROWS;
}

// ---------------- host ----------------
static void launch_gemm(const void* Ah, const void* Al, int lda,
                        const void* Bh, const void* Bl, int ldb,
                        const float* bias, float* Cf, void* Ch, void* Cl,
                        int ldc, int nPad, int nOut, int K, int relu, int mode)
{
    cudaFuncSetAttribute(gemm_bf3, cudaFuncAttributeMaxDynamicSharedMemorySize, GEMM_DYN);
    dim3 grid(nPad / 128, B_ROWS / 128);
    gemm_bf3<<<grid, 256, GEMM_DYN>>>(
        (const uint16_t*)Ah, (const uint16_t*)Al, lda,
        (const uint16_t*)Bh, (const uint16_t*)Bl, ldb,
        bias, Cf, (uint16_t*)Ch, (uint16_t*)Cl, ldc, nOut, K, relu, mode);
}

extern "C" void kernel_launch(void* const* d_in, const int* in_sizes, int n_in,
                              void* d_out, int out_size)
{
    const float* x        = (const float*)d_in[0];
    const void*  mask     = d_in[1];
    const int*   labels   = (const int*)d_in[2];
    const float* eps      = (const float*)d_in[3];
    const float* W_enc    = (const float*)d_in[4];
    const float* b_enc    = (const float*)d_in[5];
    const float* codebook = (const float*)d_in[6];
    const float* W1       = (const float*)d_in[7];
    const float* b1       = (const float*)d_in[8];
    const float* W2       = (const float*)d_in[9];
    const float* b2       = (const float*)d_in[10];
    const float* Wd       = (const float*)d_in[11];
    const float* bd       = (const float*)d_in[12];
    float* out = (float*)d_out;

    void *p_xh, *p_xl, *p_weh, *p_wel, *p_w1h, *p_w1l, *p_w2h, *p_w2l, *p_wdh, *p_wdl;
    void *p_hh, *p_hl, *p_cath, *p_catl;
    float *p_ml, *p_G, *p_lb, *p_ze, *p_zq, *p_lg, *p_kl;
    cudaGetSymbolAddress(&p_xh, g_xh);   cudaGetSymbolAddress(&p_xl, g_xl);
    cudaGetSymbolAddress(&p_weh, g_weh); cudaGetSymbolAddress(&p_wel, g_wel);
    cudaGetSymbolAddress(&p_w1h, g_w1h); cudaGetSymbolAddress(&p_w1l, g_w1l);
    cudaGetSymbolAddress(&p_w2h, g_w2h); cudaGetSymbolAddress(&p_w2l, g_w2l);
    cudaGetSymbolAddress(&p_wdh, g_wdh); cudaGetSymbolAddress(&p_wdl, g_wdl);
    cudaGetSymbolAddress(&p_hh, g_hh);   cudaGetSymbolAddress(&p_hl, g_hl);
    cudaGetSymbolAddress(&p_cath, g_cath); cudaGetSymbolAddress(&p_catl, g_catl);
    cudaGetSymbolAddress((void**)&p_ml, g_ml);
    cudaGetSymbolAddress((void**)&p_G,  g_G);
    cudaGetSymbolAddress((void**)&p_lb, g_lb);
    cudaGetSymbolAddress((void**)&p_ze, g_ze_s);
    cudaGetSymbolAddress((void**)&p_zq, g_zq_s);
    cudaGetSymbolAddress((void**)&p_lg, g_lg_s);
    cudaGetSymbolAddress((void**)&p_kl, g_kl_s);

    const size_t full_elems = (size_t)B_ROWS * (IN_DIM + ENC_DIM + ENC_DIM + KCLS) + 1;
    const bool full = ((size_t)out_size >= full_elems);
    float* xt = out;
    float* ze = full ? out + (size_t)B_ROWS * IN_DIM : p_ze;
    float* zq = full ? ze + (size_t)B_ROWS * ENC_DIM : p_zq;
    float* lg = full ? zq + (size_t)B_ROWS * ENC_DIM : p_lg;
    float* kl = full ? lg + (size_t)B_ROWS * KCLS    : p_kl;

    // ---- prep: splits + logits weights + mask mode ----
    {
        long np = (long)B_ROWS * IN_DIM / 2;
        split_mat<<<(unsigned)((np + 255) / 256), 256>>>(x, (uint32_t*)p_xh, (uint32_t*)p_xl, np, np);
        long sp = (long)ENC_DIM * IN_DIM / 2, tp = (long)ZE_NPAD * IN_DIM / 2;
        split_mat<<<(unsigned)((tp + 255) / 256), 256>>>(W_enc, (uint32_t*)p_weh, (uint32_t*)p_wel, tp, sp);
        long w1p = (long)VDIM * IN_DIM / 2;
        split_mat<<<(unsigned)((w1p + 255) / 256), 256>>>(W1, (uint32_t*)p_w1h, (uint32_t*)p_w1l, w1p, w1p);
        long w2p = (long)2 * VDIM * VDIM / 2;
        split_mat<<<(unsigned)((w2p + 255) / 256), 256>>>(W2, (uint32_t*)p_w2h, (uint32_t*)p_w2l, w2p, w2p);
        split_wd<<<(IN_DIM * (CAT_LD / 2) + 255) / 256, 256>>>(Wd);
    }
    detect_mask_kernel<<<1, 256>>>((const unsigned int*)mask);
    build_G<<<dim3(KCLS, IN_DIM / 128), 128>>>(W_enc, codebook);
    build_lb<<<KCLS, 128>>>(b_enc, codebook);

    // logits (exact fp32 via G = codebook @ W_enc)
    sgemm64<<<B_ROWS / 64, 128>>>(x, p_G, p_lb, lg);

    // z_e_x
    launch_gemm(p_xh, p_xl, IN_DIM, p_weh, p_wel, IN_DIM, b_enc,
                ze, nullptr, nullptr, ENC_DIM, ZE_NPAD, ENC_DIM, IN_DIM, 0, 0);
    // h = relu(x@W1^T + b1) -> bf16 hi/lo
    launch_gemm(p_xh, p_xl, IN_DIM, p_w1h, p_w1l, IN_DIM, b1,
                nullptr, p_hh, p_hl, VDIM, VDIM, VDIM, IN_DIM, 1, 1);
    // mu||logvar
    launch_gemm(p_hh, p_hl, VDIM, p_w2h, p_w2l, VDIM, b2,
                p_ml, nullptr, nullptr, 2 * VDIM, 2 * VDIM, 2 * VDIM, VDIM, 0, 0);

    // argmax / y / z_q (fills cat y region)
    argmax_y_kernel<<<B_ROWS, 32>>>(lg, mask, labels, codebook, zq);
    // sampled_z (fills cat z region) + KL
    vae_post_kernel<<<B_ROWS, 256>>>(eps);
    kl_reduce_kernel<<<1, 256>>>(kl);

    // decoder
    launch_gemm(p_cath, p_catl, CAT_LD, p_wdh, p_wdl, CAT_LD, bd,
                xt, nullptr, nullptr, IN_DIM, IN_DIM, IN_DIM, CAT_LD, 0, 0);
}